// round 9
// baseline (speedup 1.0000x reference)
#include <cuda_runtime.h>

// Batched active-set (water-filling) projection — warp-per-row, threshold-set
// formulation (R7 structure, proven exact) with latency-optimized scans:
//   * per-element values pre-scaled once to int (2^18 fixed point) so the
//     per-iteration accumulation is reassociable integer math,
//   * 4-way accumulator trees (serial FADD/IADD depth 32 -> ~10),
//   * set-membership compares remain on exact floats -> decisions identical
//     to the reference trajectory; sums carry the same 2^18 precision that
//     passed at rel_err 8.5e-8.
// Phase 0: lower set {y < -fill} (fill monotone decreasing).
// Phase 1: upper set {d=y-u > -fill} over the frozen complement.
// Lower-clamps poisoned to -INF in yv; upper kept in shared memory.

#define NCOLS 1024
#define EPL 32
#define WARPS_PER_BLOCK 2
#define THREADS (WARPS_PER_BLOCK * 32)

#define SCALE    262144.0f              // 2^18
#define INVSCALE (1.0f / 262144.0f)

__global__ __launch_bounds__(THREADS)
void proj_kernel(const float* __restrict__ y,
                 const float* __restrict__ upper,
                 float* __restrict__ out) {
    const int lane = threadIdx.x & 31;
    const int row  = blockIdx.x * WARPS_PER_BLOCK + (threadIdx.x >> 5);

    __shared__ float su[NCOLS];
    {
        const float4* u4 = reinterpret_cast<const float4*>(upper);
        float4*       s4 = reinterpret_cast<float4*>(su);
        #pragma unroll
        for (int k = 0; k < 4; k++)
            s4[threadIdx.x + THREADS * k] = u4[threadIdx.x + THREADS * k];
    }
    __syncthreads();   // one-time; warps independent afterwards

    const float NEG_INF = __int_as_float(0xff800000);

    float yv[EPL];
    int   yi[EPL];
    {
        const float4* yrow = reinterpret_cast<const float4*>(y + (size_t)row * NCOLS);
        #pragma unroll
        for (int k = 0; k < 8; k++) {
            const float4 a = yrow[lane + 32 * k];
            yv[4*k+0]=a.x; yv[4*k+1]=a.y; yv[4*k+2]=a.z; yv[4*k+3]=a.w;
        }
        #pragma unroll
        for (int e = 0; e < EPL; e++)
            yi[e] = __float2int_rn(yv[e] * SCALE);
    }

    // s0 = sum(y): 4-way int tree + REDUX
    float s0;
    {
        int a0 = 0, a1 = 0, a2 = 0, a3 = 0;
        #pragma unroll
        for (int e = 0; e < EPL; e += 4) {
            a0 += yi[e+0]; a1 += yi[e+1]; a2 += yi[e+2]; a3 += yi[e+3];
        }
        const int si = __reduce_add_sync(0xffffffffu, (a0 + a1) + (a2 + a3));
        s0 = (float)si * INVSCALE;
    }

    const float base0 = 512.0f - s0;
    float fill = base0 * (1.0f / 1024.0f);

    int   it = 0;
    float maskT0 = 0.0f;
    bool  p0conv = false;
    float cntF = 0.0f, dsF = 0.0f;

    // ---- phase 0: lower clamps (threshold scan on y) ----
    {
        int prev = 0;
        for (;;) {
            ++it;
            const float T = -fill;
            int c0=0,c1=0,c2=0,c3=0, d0=0,d1=0,d2=0,d3=0;
            #pragma unroll
            for (int e = 0; e < EPL; e += 4) {
                const bool p0 = yv[e+0] < T, p1 = yv[e+1] < T,
                           p2 = yv[e+2] < T, p3 = yv[e+3] < T;
                c0 += p0; c1 += p1; c2 += p2; c3 += p3;
                d0 += p0 ? yi[e+0] : 0; d1 += p1 ? yi[e+1] : 0;
                d2 += p2 ? yi[e+2] : 0; d3 += p3 ? yi[e+3] : 0;
            }
            const int cr = __reduce_add_sync(0xffffffffu, (c0+c1)+(c2+c3));
            const int dr = __reduce_add_sync(0xffffffffu, (d0+d1)+(d2+d3));
            const float D = (float)dr * INVSCALE;
            maskT0 = T; cntF = (float)cr; dsF = D;
            if (cr == prev) { p0conv = true; break; }   // phase-advance round
            prev = cr;
            fill = __fdividef(base0 + D, fmaxf(1024.0f - (float)cr, 1.0f));
            if (it >= 32) break;                         // budget exhausted
        }
    }

    float4* orow = reinterpret_cast<float4*>(out + (size_t)row * NCOLS);
    const float4* su4 = reinterpret_cast<const float4*>(su);

    if (p0conv && it < 32) {
        // phase transition: yv <- d = y-u (free) / -INF (lower-clamped);
        // yi <- round(d*2^18) (0 for poisoned; never selected since -INF > T
        // is false).
        #pragma unroll
        for (int k = 0; k < 8; k++) {
            const float4 u4 = su4[lane + 32 * k];
            const float uu[4] = {u4.x, u4.y, u4.z, u4.w};
            #pragma unroll
            for (int j = 0; j < 4; j++) {
                const int e = 4 * k + j;
                const bool lo = yv[e] < maskT0;
                const float d = yv[e] - uu[j];
                yv[e] = lo ? NEG_INF : d;
                yi[e] = lo ? 0 : __float2int_rn(d * SCALE);
            }
        }
        const float base1 = base0 + dsF;
        const float n1    = 1024.0f - cntF;

        // ---- phase 1: upper clamps (threshold scan on d) ----
        float maskT1 = 0.0f;
        {
            int prev1 = 0;
            for (;;) {
                ++it;
                const float T = -fill;
                int c0=0,c1=0,c2=0,c3=0, d0=0,d1=0,d2=0,d3=0;
                #pragma unroll
                for (int e = 0; e < EPL; e += 4) {
                    const bool p0 = yv[e+0] > T, p1 = yv[e+1] > T,
                               p2 = yv[e+2] > T, p3 = yv[e+3] > T;
                    c0 += p0; c1 += p1; c2 += p2; c3 += p3;
                    d0 += p0 ? yi[e+0] : 0; d1 += p1 ? yi[e+1] : 0;
                    d2 += p2 ? yi[e+2] : 0; d3 += p3 ? yi[e+3] : 0;
                }
                const int cr = __reduce_add_sync(0xffffffffu, (c0+c1)+(c2+c3));
                const int ar = __reduce_add_sync(0xffffffffu, (d0+d1)+(d2+d3));
                const float A = (float)ar * INVSCALE;
                maskT1 = T;
                if (cr == prev1) break;
                prev1 = cr;
                fill = __fdividef(base1 + A, fmaxf(n1 - (float)cr, 1.0f));
                if (it >= 32) break;
            }
        }

        // epilogue: yv holds d. lower (-INF) -> 0; upper (d > T1) -> u;
        // free -> y + fill = d + u + fill
        #pragma unroll
        for (int k = 0; k < 8; k++) {
            const float4 u4 = su4[lane + 32 * k];
            const float uu[4] = {u4.x, u4.y, u4.z, u4.w};
            float o4[4];
            #pragma unroll
            for (int j = 0; j < 4; j++) {
                const int e = 4 * k + j;
                const float d = yv[e];
                o4[j] = (d == NEG_INF) ? 0.0f
                      : ((d > maskT1) ? uu[j] : d + uu[j] + fill);
            }
            float4 v; v.x=o4[0]; v.y=o4[1]; v.z=o4[2]; v.w=o4[3];
            orow[lane + 32 * k] = v;
        }
    } else {
        // phase 1 never ran (budget exhausted in phase 0)
        #pragma unroll
        for (int k = 0; k < 8; k++) {
            float o4[4];
            #pragma unroll
            for (int j = 0; j < 4; j++) {
                const int e = 4 * k + j;
                o4[j] = (yv[e] < maskT0) ? 0.0f : yv[e] + fill;
            }
            float4 v; v.x=o4[0]; v.y=o4[1]; v.z=o4[2]; v.w=o4[3];
            orow[lane + 32 * k] = v;
        }
    }
}

extern "C" void kernel_launch(void* const* d_in, const int* in_sizes, int n_in,
                              void* d_out, int out_size) {
    const float* y     = (const float*)d_in[0];
    const float* upper = (const float*)d_in[1];
    float*       out   = (float*)d_out;
    const int rows   = in_sizes[0] / NCOLS;                      // 2048
    const int blocks = (rows + WARPS_PER_BLOCK - 1) / WARPS_PER_BLOCK;
    proj_kernel<<<blocks, THREADS>>>(y, upper, out);
}

// round 10
// speedup vs baseline: 1.1910x; 1.1910x over previous
#include <cuda_runtime.h>

// Batched active-set (water-filling) projection — warp-per-row, threshold-set
// formulation. Identical structure to the 11.0us R7 winner; the only change
// is the per-iteration scan: 4-way accumulator trees (serial FADD depth
// 32 -> 8+2) and parallel F2I on the four partials before a 2-level integer
// merge + REDUX. Cost: +~6 registers, no extra arrays.
//
// Phase 0: lower set {y < -fill}, fill monotone decreasing.
// Phase 1: upper set {d = y-u > -fill} over the frozen phase-0 complement,
//          fill monotone increasing. Lower-clamps poisoned to -INF in yv.
// upper lives in shared memory (row-invariant). Reductions: exact 2^18
// fixed-point REDUX.ADD; water level via __fdividef.

#define NCOLS 1024
#define EPL 32
#define WARPS_PER_BLOCK 2
#define THREADS (WARPS_PER_BLOCK * 32)

#define SCALE    262144.0f              // 2^18
#define INVSCALE (1.0f / 262144.0f)

__global__ __launch_bounds__(THREADS)
void proj_kernel(const float* __restrict__ y,
                 const float* __restrict__ upper,
                 float* __restrict__ out) {
    const int lane = threadIdx.x & 31;
    const int row  = blockIdx.x * WARPS_PER_BLOCK + (threadIdx.x >> 5);

    __shared__ float su[NCOLS];
    {
        const float4* u4 = reinterpret_cast<const float4*>(upper);
        float4*       s4 = reinterpret_cast<float4*>(su);
        #pragma unroll
        for (int k = 0; k < 4; k++)
            s4[threadIdx.x + THREADS * k] = u4[threadIdx.x + THREADS * k];
    }
    __syncthreads();   // one-time; warps independent afterwards

    const float NEG_INF = __int_as_float(0xff800000);

    float yv[EPL];
    {
        const float4* yrow = reinterpret_cast<const float4*>(y + (size_t)row * NCOLS);
        #pragma unroll
        for (int k = 0; k < 8; k++) {
            const float4 a = yrow[lane + 32 * k];
            yv[4*k+0]=a.x; yv[4*k+1]=a.y; yv[4*k+2]=a.z; yv[4*k+3]=a.w;
        }
    }

    // s0 = sum(y): 4-way tree, parallel F2I, REDUX
    float s0;
    {
        float a0=0.f, a1=0.f, a2=0.f, a3=0.f;
        #pragma unroll
        for (int e = 0; e < EPL; e += 4) {
            a0 += yv[e+0]; a1 += yv[e+1]; a2 += yv[e+2]; a3 += yv[e+3];
        }
        const int i0 = __float2int_rn(a0 * SCALE), i1 = __float2int_rn(a1 * SCALE);
        const int i2 = __float2int_rn(a2 * SCALE), i3 = __float2int_rn(a3 * SCALE);
        const int si = __reduce_add_sync(0xffffffffu, (i0+i1)+(i2+i3));
        s0 = (float)si * INVSCALE;
    }

    const float base0 = 512.0f - s0;
    float fill = base0 * (1.0f / 1024.0f);

    int   it = 0;
    float maskT0 = 0.0f;
    bool  p0conv = false;
    float cntF = 0.0f, dsF = 0.0f;

    // ---- phase 0: lower clamps (threshold scan on y) ----
    {
        int prev = 0;
        for (;;) {
            ++it;
            const float T = -fill;
            int   c0=0,c1=0,c2=0,c3=0;
            float d0=0.f,d1=0.f,d2=0.f,d3=0.f;
            #pragma unroll
            for (int e = 0; e < EPL; e += 4) {
                const bool p0 = yv[e+0] < T, p1 = yv[e+1] < T,
                           p2 = yv[e+2] < T, p3 = yv[e+3] < T;
                c0 += p0; c1 += p1; c2 += p2; c3 += p3;
                d0 += p0 ? yv[e+0] : 0.f; d1 += p1 ? yv[e+1] : 0.f;
                d2 += p2 ? yv[e+2] : 0.f; d3 += p3 ? yv[e+3] : 0.f;
            }
            const int j0 = __float2int_rn(d0 * SCALE), j1 = __float2int_rn(d1 * SCALE);
            const int j2 = __float2int_rn(d2 * SCALE), j3 = __float2int_rn(d3 * SCALE);
            const int cr = __reduce_add_sync(0xffffffffu, (c0+c1)+(c2+c3));
            const int dr = __reduce_add_sync(0xffffffffu, (j0+j1)+(j2+j3));
            const float D = (float)dr * INVSCALE;
            maskT0 = T; cntF = (float)cr; dsF = D;
            if (cr == prev) { p0conv = true; break; }   // phase-advance round
            prev = cr;
            fill = __fdividef(base0 + D, fmaxf(1024.0f - (float)cr, 1.0f));
            if (it >= 32) break;                         // budget exhausted
        }
    }

    float4* orow = reinterpret_cast<float4*>(out + (size_t)row * NCOLS);
    const float4* su4 = reinterpret_cast<const float4*>(su);

    if (p0conv && it < 32) {
        // phase transition: yv <- d = y-u (free) / -INF (lower-clamped)
        #pragma unroll
        for (int k = 0; k < 8; k++) {
            const float4 u4 = su4[lane + 32 * k];
            const float uu[4] = {u4.x, u4.y, u4.z, u4.w};
            #pragma unroll
            for (int j = 0; j < 4; j++) {
                const int e = 4 * k + j;
                yv[e] = (yv[e] < maskT0) ? NEG_INF : (yv[e] - uu[j]);
            }
        }
        const float base1 = base0 + dsF;
        const float n1    = 1024.0f - cntF;

        // ---- phase 1: upper clamps (threshold scan on d) ----
        // note: poisoned entries are -INF -> (d > T) false, and the selected
        // accumulation never touches them, so no masking needed.
        float maskT1 = 0.0f;
        {
            int prev1 = 0;
            for (;;) {
                ++it;
                const float T = -fill;
                int   c0=0,c1=0,c2=0,c3=0;
                float d0=0.f,d1=0.f,d2=0.f,d3=0.f;
                #pragma unroll
                for (int e = 0; e < EPL; e += 4) {
                    const bool p0 = yv[e+0] > T, p1 = yv[e+1] > T,
                               p2 = yv[e+2] > T, p3 = yv[e+3] > T;
                    c0 += p0; c1 += p1; c2 += p2; c3 += p3;
                    d0 += p0 ? yv[e+0] : 0.f; d1 += p1 ? yv[e+1] : 0.f;
                    d2 += p2 ? yv[e+2] : 0.f; d3 += p3 ? yv[e+3] : 0.f;
                }
                const int j0 = __float2int_rn(d0 * SCALE), j1 = __float2int_rn(d1 * SCALE);
                const int j2 = __float2int_rn(d2 * SCALE), j3 = __float2int_rn(d3 * SCALE);
                const int cr = __reduce_add_sync(0xffffffffu, (c0+c1)+(c2+c3));
                const int ar = __reduce_add_sync(0xffffffffu, (j0+j1)+(j2+j3));
                const float A = (float)ar * INVSCALE;
                maskT1 = T;
                if (cr == prev1) break;
                prev1 = cr;
                fill = __fdividef(base1 + A, fmaxf(n1 - (float)cr, 1.0f));
                if (it >= 32) break;
            }
        }

        // epilogue: yv holds d. lower (-INF) -> 0; upper (d > T1) -> u;
        // free -> y + fill = d + u + fill
        #pragma unroll
        for (int k = 0; k < 8; k++) {
            const float4 u4 = su4[lane + 32 * k];
            const float uu[4] = {u4.x, u4.y, u4.z, u4.w};
            float o4[4];
            #pragma unroll
            for (int j = 0; j < 4; j++) {
                const int e = 4 * k + j;
                const float d = yv[e];
                o4[j] = (d == NEG_INF) ? 0.0f
                      : ((d > maskT1) ? uu[j] : d + uu[j] + fill);
            }
            float4 v; v.x=o4[0]; v.y=o4[1]; v.z=o4[2]; v.w=o4[3];
            orow[lane + 32 * k] = v;
        }
    } else {
        // phase 1 never ran (budget exhausted in phase 0)
        #pragma unroll
        for (int k = 0; k < 8; k++) {
            float o4[4];
            #pragma unroll
            for (int j = 0; j < 4; j++) {
                const int e = 4 * k + j;
                o4[j] = (yv[e] < maskT0) ? 0.0f : yv[e] + fill;
            }
            float4 v; v.x=o4[0]; v.y=o4[1]; v.z=o4[2]; v.w=o4[3];
            orow[lane + 32 * k] = v;
        }
    }
}

extern "C" void kernel_launch(void* const* d_in, const int* in_sizes, int n_in,
                              void* d_out, int out_size) {
    const float* y     = (const float*)d_in[0];
    const float* upper = (const float*)d_in[1];
    float*       out   = (float*)d_out;
    const int rows   = in_sizes[0] / NCOLS;                      // 2048
    const int blocks = (rows + WARPS_PER_BLOCK - 1) / WARPS_PER_BLOCK;
    proj_kernel<<<blocks, THREADS>>>(y, upper, out);
}